// round 5
// baseline (speedup 1.0000x reference)
#include <cuda_runtime.h>
#include <cuda_bf16.h>

// Output[b,s,:] == mean(knowledge, axis=0) for every (b,s):
// top_k with max_chunks == K selects a permutation of ALL knowledge rows,
// so mean(take(knowledge, top_k), axis=1) == mean(knowledge, axis=0).
//
// R1-R4 evidence: total dur_us is pinned at a ~8.93us graph-replay floor
// regardless of kernel contents (identical to the ns across 4 variants).
// Remaining lever: minimize true kernel latency. This version splits the
// 64-row reduction across 4 warp-groups (16 loads/thread, not 64),
// combines partials via smem, and spreads the store tail over 512 threads.

#define E_DIM 512
#define K_ROWS 64
#define THREADS 512            // 4 groups of 128; 128 float4 columns
#define ROWS_PER_CTA 16        // 4096 / 16 = 256 CTAs
#define COLS4 (E_DIM / 4)      // 128 float4 per row

__global__ void __launch_bounds__(THREADS)
fused_mean_broadcast(const float4* __restrict__ knowledge4,
                     float4* __restrict__ out, int rows) {
    __shared__ float4 part[4 * COLS4];   // 4 partial sums per column, 8KB

    int t = threadIdx.x;
    int c = t & (COLS4 - 1);   // column 0..127
    int q = t >> 7;            // group 0..3: rows [16q, 16q+16)

    // Each thread sums 16 rows of its column: 16 independent loads,
    // fully unrolled -> one exposed memory latency.
    float4 s = make_float4(0.f, 0.f, 0.f, 0.f);
#pragma unroll
    for (int k = 0; k < K_ROWS / 4; ++k) {
        float4 a = knowledge4[(q * (K_ROWS / 4) + k) * COLS4 + c];
        s.x += a.x; s.y += a.y; s.z += a.z; s.w += a.w;
    }
    part[q * COLS4 + c] = s;
    __syncthreads();

    // Every thread forms the full column mean from the 4 partials
    // (redundant across groups, but only 3 float4 adds from smem).
    float4 p0 = part[0 * COLS4 + c];
    float4 p1 = part[1 * COLS4 + c];
    float4 p2 = part[2 * COLS4 + c];
    float4 p3 = part[3 * COLS4 + c];
    const float inv = 1.0f / (float)K_ROWS;
    float4 m;
    m.x = (p0.x + p1.x + p2.x + p3.x) * inv;
    m.y = (p0.y + p1.y + p2.y + p3.y) * inv;
    m.z = (p0.z + p1.z + p2.z + p3.z) * inv;
    m.w = (p0.w + p1.w + p2.w + p3.w) * inv;

    // CTA writes 16 identical rows; group q writes rows [4q, 4q+4).
    int r0 = blockIdx.x * ROWS_PER_CTA;
    size_t base = (size_t)(r0 + q * 4) * COLS4 + c;
#pragma unroll
    for (int r = 0; r < 4; ++r) {
        if (r0 + q * 4 + r < rows)
            out[base + (size_t)r * COLS4] = m;
    }
}

extern "C" void kernel_launch(void* const* d_in, const int* in_sizes, int n_in,
                              void* d_out, int out_size) {
    // d_in[0]: query_embedding [4,1024,512] f32 (unused — output is query-independent)
    // d_in[1]: knowledge [64,512] f32
    const float* knowledge = (const float*)d_in[1];
    float* out = (float*)d_out;

    int rows = out_size / E_DIM;                           // 4096
    int blocks = (rows + ROWS_PER_CTA - 1) / ROWS_PER_CTA; // 256

    fused_mean_broadcast<<<blocks, THREADS>>>(
        reinterpret_cast<const float4*>(knowledge),
        reinterpret_cast<float4*>(out), rows);
}